// round 11
// baseline (speedup 1.0000x reference)
#include <cuda_runtime.h>
#include <cuda_fp16.h>
#include <cstdint>

#define BATCH 8
#define SEQ   4096
#define EMB   128
#define DH    24
#define TQ    32
// (1/sqrt(128)) * log2(e): folded into Q so softmax is exp2
#define QSCALE (0.08838834764831845f * 1.4426950408889634f)

// Packed fp16 projected tensors (24 cols, no padding).  K and V share one
// array so attention staging needs a single base pointer.
#define KVH (BATCH*SEQ*DH)
__device__ __align__(16) __half Qh_g[BATCH*SEQ*DH];
__device__ __align__(16) __half KV_g[2*KVH];      // [0..KVH) = K, [KVH..) = V

// ---------------- helpers ----------------------------------------------------
__device__ __forceinline__ uint32_t smem_u32(const void* p) {
    uint32_t a;
    asm("{ .reg .u64 t; cvta.to.shared.u64 t, %1; cvt.u32.u64 %0, t; }" : "=r"(a) : "l"(p));
    return a;
}
__device__ __forceinline__ void ldsm4(uint32_t* r, uint32_t a) {
    asm volatile("ldmatrix.sync.aligned.m8n8.x4.shared.b16 {%0,%1,%2,%3}, [%4];"
        : "=r"(r[0]), "=r"(r[1]), "=r"(r[2]), "=r"(r[3]) : "r"(a));
}
__device__ __forceinline__ void ldsm2(uint32_t* r, uint32_t a) {
    asm volatile("ldmatrix.sync.aligned.m8n8.x2.shared.b16 {%0,%1}, [%2];"
        : "=r"(r[0]), "=r"(r[1]) : "r"(a));
}
__device__ __forceinline__ void ldsm4t(uint32_t* r, uint32_t a) {
    asm volatile("ldmatrix.sync.aligned.m8n8.x4.trans.shared.b16 {%0,%1,%2,%3}, [%4];"
        : "=r"(r[0]), "=r"(r[1]), "=r"(r[2]), "=r"(r[3]) : "r"(a));
}
__device__ __forceinline__ void ldsm2t(uint32_t* r, uint32_t a) {
    asm volatile("ldmatrix.sync.aligned.m8n8.x2.trans.shared.b16 {%0,%1}, [%2];"
        : "=r"(r[0]), "=r"(r[1]) : "r"(a));
}
__device__ __forceinline__ void mma16816(float* c, const uint32_t* a, const uint32_t* b) {
    asm volatile("mma.sync.aligned.m16n8k16.row.col.f32.f16.f16.f32 "
        "{%0,%1,%2,%3}, {%4,%5,%6,%7}, {%8,%9}, {%0,%1,%2,%3};"
        : "+f"(c[0]), "+f"(c[1]), "+f"(c[2]), "+f"(c[3])
        : "r"(a[0]), "r"(a[1]), "r"(a[2]), "r"(a[3]), "r"(b[0]), "r"(b[1]));
}
__device__ __forceinline__ uint32_t pack2h(float lo_e, float hi_e) { // lo_e -> low half
    uint32_t r; asm("cvt.rn.f16x2.f32 %0, %1, %2;" : "=r"(r) : "f"(hi_e), "f"(lo_e)); return r;
}
__device__ __forceinline__ uint32_t h2exp2u(uint32_t x) {
    uint32_t r; asm("ex2.approx.f16x2 %0, %1;" : "=r"(r) : "r"(x)); return r;
}
__device__ __forceinline__ float2 h2sumf(uint32_t a, uint32_t b) {
    __half2 s = __hadd2(*reinterpret_cast<__half2*>(&a), *reinterpret_cast<__half2*>(&b));
    return __half22float2(s);
}
__device__ __forceinline__ void cpasync16(uint32_t dst, const void* src) {
    asm volatile("cp.async.cg.shared.global [%0], [%1], 16;" :: "r"(dst), "l"(src));
}
#define CP_COMMIT() asm volatile("cp.async.commit_group;" ::: "memory")

// ---------------------------------------------------------------------------
// Kernel 1: Q/K/V projection on tensor cores (fp16 in/out, fp32 accum),
// writing PACKED 24-col fp16 outputs.
// ---------------------------------------------------------------------------
#define PR     64
#define PSTR   272
#define WSOFF  (PR * PSTR)
#define PSMTOT (WSOFF + 72 * PSTR)

__global__ __launch_bounds__(128) void proj_kernel(
    const float* __restrict__ x,
    const float* __restrict__ wQ, const float* __restrict__ bQ,
    const float* __restrict__ wK, const float* __restrict__ bK,
    const float* __restrict__ wV, const float* __restrict__ bV)
{
    __shared__ __align__(16) unsigned char psm[PSMTOT];
    __shared__ float bias[72];
    const uint32_t smb = smem_u32(psm);

    int tid = threadIdx.x, l = tid & 31, w = tid >> 5;
    int row0 = blockIdx.x * PR;

    const float4* xg = reinterpret_cast<const float4*>(x + (size_t)row0 * EMB);
    #pragma unroll
    for (int j = 0; j < 16; j++) {
        int i = tid + 128*j;
        int r = i >> 5, c4 = i & 31;
        float4 v = __ldg(xg + (size_t)r*32 + c4);
        uint2 o = make_uint2(pack2h(v.x, v.y), pack2h(v.z, v.w));
        *reinterpret_cast<uint2*>(psm + r*PSTR + c4*8) = o;
    }

    for (int i = tid; i < 72*64; i += 128) {
        int n = i / 64, k2 = i % 64;
        const float* wsrc; int c;
        if (n < 24)      { wsrc = wQ; c = n; }
        else if (n < 48) { wsrc = wK; c = n - 24; }
        else             { wsrc = wV; c = n - 48; }
        float f0 = __ldg(&wsrc[(2*k2)*DH + c]);
        float f1 = __ldg(&wsrc[(2*k2+1)*DH + c]);
        *reinterpret_cast<uint32_t*>(psm + WSOFF + n*PSTR + k2*4) = pack2h(f0, f1);
    }
    if (tid < 24) { bias[tid] = bQ[tid]; bias[24+tid] = bK[tid]; bias[48+tid] = bV[tid]; }
    __syncthreads();

    float c[9][4];
    #pragma unroll
    for (int nt = 0; nt < 9; nt++)
        #pragma unroll
        for (int q = 0; q < 4; q++) c[nt][q] = 0.f;

    int lq = l & 15;
    uint32_t a_off  = (uint32_t)((l & 15)*PSTR + (l >> 4)*16);
    uint32_t b_off  = (uint32_t)(((l & 7) + ((l >> 4) << 3))*PSTR + ((l >> 3) & 1)*16);
    uint32_t b2_off = (uint32_t)((lq & 7)*PSTR + ((lq >> 3) & 1)*16);

    #pragma unroll
    for (int ks = 0; ks < 8; ks++) {
        uint32_t qa[4];
        ldsm4(qa, smb + (uint32_t)(16*w*PSTR + ks*32) + a_off);
        #pragma unroll
        for (int ng = 0; ng < 4; ng++) {
            uint32_t bb[4];
            ldsm4(bb, smb + WSOFF + (uint32_t)(ng*16*PSTR + ks*32) + b_off);
            mma16816(c[2*ng],   qa, bb);
            mma16816(c[2*ng+1], qa, bb + 2);
        }
        uint32_t b2[2];
        ldsm2(b2, smb + WSOFF + (uint32_t)(64*PSTR + ks*32) + b2_off);
        mma16816(c[8], qa, b2);
    }

    int r0 = row0 + 16*w + (l >> 2);
    #pragma unroll
    for (int nt = 0; nt < 9; nt++) {
        int col = nt*8 + 2*(l & 3);
        __half* dst; int cc; float sc;
        if (col < 24)      { dst = Qh_g;        cc = col;      sc = QSCALE; }
        else if (col < 48) { dst = KV_g;        cc = col - 24; sc = 1.f; }
        else               { dst = KV_g + KVH;  cc = col - 48; sc = 1.f; }
        float b0 = bias[col], b1 = bias[col+1];
        *reinterpret_cast<uint32_t*>(dst + (size_t)r0*DH + cc) =
            pack2h((c[nt][0] + b0)*sc, (c[nt][1] + b1)*sc);
        *reinterpret_cast<uint32_t*>(dst + (size_t)(r0+8)*DH + cc) =
            pack2h((c[nt][2] + b0)*sc, (c[nt][3] + b1)*sc);
    }
}

// ---------------------------------------------------------------------------
// Kernel 2: fp16 attention, TQ=32, warp-independent KV-range split.
// Warp w owns KV rows [w*1024, (w+1)*1024) streamed as 64 private 16-row
// tiles (double-buffered cp.async, no CTA barriers in the mainloop).
// smem k-pad cols (bytes 48..63 of each 80B row) are zeroed once.
// ---------------------------------------------------------------------------
#define ROWB  80
#define WTK   16
#define NWT   64
#define MATK  (WTK*ROWB)          /* 1280: one 16x(24+pad) fp16 matrix */
#define WBUF  (2*MATK)            /* 2560: K|V for one tile            */
#define KVOFF (TQ*ROWB)           /* 2560: after Q                     */
#define KVEND (KVOFF + 4*2*WBUF)  /* 23040                             */
#define HPW   896                 /* 32*28 floats per warp partial     */
#define WOOFF 14336               /* after 4 warp H partials           */
#define SMTOT (WOOFF + DH*EMB*4 + 512)   /* 27136 */
#define HSTR  28

__global__ __launch_bounds__(128, 5) void attn_kernel(
    const float* __restrict__ wO, const float* __restrict__ bO,
    float* __restrict__ out)
{
    __shared__ __align__(16) unsigned char sm[SMTOT];
    __shared__ float lsum_sh[TQ];
    const uint32_t smb = smem_u32(sm);

    int tid = threadIdx.x, l = tid & 31, w = tid >> 5;
    int b = blockIdx.y, q0 = blockIdx.x * TQ;

    // ---- zero-init Q + KV staging region (k-pad must be 0 for the mma k32)
    {
        uint4 z = make_uint4(0,0,0,0);
        for (int i = tid; i < KVEND/16; i += 128)
            reinterpret_cast<uint4*>(sm)[i] = z;
    }
    if (tid < TQ) lsum_sh[tid] = 0.f;
    __syncthreads();

    // ---- per-lane staging precompute: 3 x 16B chunks (48B K + 48B V rows)
    const uint32_t mybuf = smb + KVOFF + (uint32_t)w*2*WBUF;
    const int kvrow0 = b*SEQ + w*(SEQ/4);
    const char* gbase = reinterpret_cast<const char*>(KV_g);
    uint32_t goff[3], doff[3];
    #pragma unroll
    for (int j = 0; j < 3; j++) {
        int idx = l + 32*j;              // 0..95
        int m = idx / 48, rem = idx % 48;
        int r = rem / 3, cch = rem % 3;
        goff[j] = (uint32_t)(m*(KVH*2) + (kvrow0 + r)*(DH*2) + cch*16);
        doff[j] = (uint32_t)(m*MATK + r*ROWB + cch*16);
    }
    auto stage_tile = [&](int t, uint32_t dst) {
        uint32_t gadd = (uint32_t)(t*WTK*DH*2);
        #pragma unroll
        for (int j = 0; j < 3; j++)
            cpasync16(dst + doff[j], gbase + goff[j] + gadd);
        CP_COMMIT();
    };
    stage_tile(0, mybuf);

    // ---- stage Q (32 rows x 48B packed)
    if (tid < 96) {
        int r = tid / 3, cch = tid % 3;
        *reinterpret_cast<uint4*>(sm + r*ROWB + cch*16) =
            *reinterpret_cast<const uint4*>(Qh_g + (size_t)(b*SEQ + q0 + r)*DH + cch*8);
    }
    __syncthreads();

    // ---- Q fragments: 2 m-tiles x 2 k-slices (16 regs)
    uint32_t qa[2][2][4];
    {
        uint32_t qoff = (uint32_t)((l & 15)*ROWB + (l >> 4)*16);
        #pragma unroll
        for (int mi = 0; mi < 2; mi++) {
            ldsm4(qa[mi][0], smb + (uint32_t)(16*mi*ROWB) + qoff);
            ldsm4(qa[mi][1], smb + (uint32_t)(16*mi*ROWB + 32) + qoff);
        }
    }

    uint32_t k_off = (uint32_t)(((l & 7) + ((l >> 4) << 3))*ROWB + ((l >> 3) & 1)*16);
    uint32_t v_off = (uint32_t)((l & 15)*ROWB + (l >> 4)*16);
    uint32_t v2off = (uint32_t)((l & 15)*ROWB + 32);

    float h[2][3][4];
    #pragma unroll
    for (int mi = 0; mi < 2; mi++)
        #pragma unroll
        for (int nt = 0; nt < 3; nt++)
            #pragma unroll
            for (int c = 0; c < 4; c++) h[mi][nt][c] = 0.f;
    float rsum[2][2] = {{0.f,0.f},{0.f,0.f}};

    // ---- mainloop: warp-private, barrier-free
    #pragma unroll 1
    for (int t = 0; t < NWT; t++) {
        uint32_t buf = mybuf + (uint32_t)(t & 1)*WBUF;
        if (t + 1 < NWT) {
            stage_tile(t + 1, mybuf + (uint32_t)((t+1) & 1)*WBUF);
            asm volatile("cp.async.wait_group 1;" ::: "memory");
        } else {
            asm volatile("cp.async.wait_group 0;" ::: "memory");
        }
        __syncwarp();

        uint32_t kh0[4], kh1[4], vh[4], vh2[2];
        ldsm4(kh0, buf + k_off);            // K rows 0..15, k 0..15
        ldsm4(kh1, buf + 32 + k_off);       // K rows 0..15, k 16..31 (pad 0)
        ldsm4t(vh,  buf + MATK + v_off);    // V k-rows 0..15, n 0..15
        ldsm2t(vh2, buf + MATK + v2off);    // V k-rows 0..15, n 16..23

        #pragma unroll
        for (int mi = 0; mi < 2; mi++) {
            float s2[8] = {0.f,0.f,0.f,0.f,0.f,0.f,0.f,0.f};
            mma16816(s2,     qa[mi][0], kh0);
            mma16816(s2 + 4, qa[mi][0], kh0 + 2);
            mma16816(s2,     qa[mi][1], kh1);
            mma16816(s2 + 4, qa[mi][1], kh1 + 2);

            uint32_t pa[4];
            pa[0] = h2exp2u(pack2h(s2[0], s2[1]));
            pa[1] = h2exp2u(pack2h(s2[2], s2[3]));
            pa[2] = h2exp2u(pack2h(s2[4], s2[5]));
            pa[3] = h2exp2u(pack2h(s2[6], s2[7]));

            float2 f0 = h2sumf(pa[0], pa[2]);
            float2 f1 = h2sumf(pa[1], pa[3]);
            rsum[mi][0] += f0.x + f0.y;
            rsum[mi][1] += f1.x + f1.y;

            mma16816(h[mi][0], pa, vh);
            mma16816(h[mi][1], pa, vh + 2);
            mma16816(h[mi][2], pa, vh2);
        }
    }

    __syncthreads();   // KV buffers dead; safe to overwrite

    // ---- per-warp H partials + lsum atomics
    float* Hp = reinterpret_cast<float*>(sm);
    {
        float* base = Hp + w*HPW;
        #pragma unroll
        for (int mi = 0; mi < 2; mi++) {
            int row = 16*mi + (l >> 2);
            #pragma unroll
            for (int nt = 0; nt < 3; nt++) {
                int col = nt*8 + 2*(l & 3);
                base[row*HSTR + col]       = h[mi][nt][0];
                base[row*HSTR + col + 1]   = h[mi][nt][1];
                base[(row+8)*HSTR + col]   = h[mi][nt][2];
                base[(row+8)*HSTR + col+1] = h[mi][nt][3];
            }
        }
        #pragma unroll
        for (int mi = 0; mi < 2; mi++) {
            float r0 = rsum[mi][0], r1 = rsum[mi][1];
            r0 += __shfl_xor_sync(0xffffffffu, r0, 1);
            r0 += __shfl_xor_sync(0xffffffffu, r0, 2);
            r1 += __shfl_xor_sync(0xffffffffu, r1, 1);
            r1 += __shfl_xor_sync(0xffffffffu, r1, 2);
            if ((l & 3) == 0) {
                atomicAdd(&lsum_sh[16*mi + (l >> 2)],     r0);
                atomicAdd(&lsum_sh[16*mi + 8 + (l >> 2)], r1);
            }
        }
    }
    __syncthreads();

    // ---- reduce 4 warp partials + normalize; stage wO/bO
    for (int i = tid; i < TQ*DH; i += 128) {
        int q = i / DH, d = i % DH;
        float v = Hp[q*HSTR + d] + Hp[HPW + q*HSTR + d]
                + Hp[2*HPW + q*HSTR + d] + Hp[3*HPW + q*HSTR + d];
        Hp[q*HSTR + d] = v * __fdividef(1.f, lsum_sh[q]);
    }
    float* wOs = reinterpret_cast<float*>(sm + WOOFF);
    float* bOs = wOs + DH*EMB;
    for (int i = tid; i < DH*EMB; i += 128) wOs[i] = wO[i];
    if (tid < EMB) bOs[tid] = bO[tid];
    __syncthreads();

    // ---- fused output projection: out[32][128]
    int e = tid;
    float wcol[DH];
    #pragma unroll
    for (int d = 0; d < DH; d++) wcol[d] = wOs[d*EMB + e];
    float be = bOs[e];
    float* op = out + ((size_t)(b*SEQ + q0))*EMB + e;
    for (int q = 0; q < TQ; q++) {
        const float4* hr = reinterpret_cast<const float4*>(Hp + q*HSTR);
        float acc = be;
        #pragma unroll
        for (int d4 = 0; d4 < 6; d4++) {
            float4 hv = hr[d4];
            acc = fmaf(hv.x, wcol[4*d4],   acc);
            acc = fmaf(hv.y, wcol[4*d4+1], acc);
            acc = fmaf(hv.z, wcol[4*d4+2], acc);
            acc = fmaf(hv.w, wcol[4*d4+3], acc);
        }
        op[(size_t)q*EMB] = acc;
    }
}

// ---------------------------------------------------------------------------
extern "C" void kernel_launch(void* const* d_in, const int* in_sizes, int n_in,
                              void* d_out, int out_size)
{
    const float* x  = (const float*)d_in[0];
    const float* wQ = (const float*)d_in[1];
    const float* bQ = (const float*)d_in[2];
    const float* wK = (const float*)d_in[3];
    const float* bK = (const float*)d_in[4];
    const float* wV = (const float*)d_in[5];
    const float* bV = (const float*)d_in[6];
    const float* wO = (const float*)d_in[7];
    const float* bO = (const float*)d_in[8];
    float* out = (float*)d_out;

    proj_kernel<<<BATCH*SEQ/PR, 128>>>(x, wQ, bQ, wK, bK, wV, bV);
    attn_kernel<<<dim3(SEQ/TQ, BATCH), 128>>>(wO, bO, out);
}

// round 14
// speedup vs baseline: 1.9409x; 1.9409x over previous
#include <cuda_runtime.h>
#include <cuda_fp16.h>
#include <cstdint>

#define BATCH 8
#define SEQ   4096
#define EMB   128
#define DH    24
#define TQ    64
// (1/sqrt(128)) * log2(e): folded into Q so softmax is exp2
#define QSCALE (0.08838834764831845f * 1.4426950408889634f)

// Packed fp16 projected tensors (24 cols).  K and V share one array.
#define KVH (BATCH*SEQ*DH)
__device__ __align__(16) __half Qh_g[BATCH*SEQ*DH];
__device__ __align__(16) __half KV_g[2*KVH];      // [0..KVH) = K, [KVH..) = V

// ---------------- helpers ----------------------------------------------------
__device__ __forceinline__ uint32_t smem_u32(const void* p) {
    uint32_t a;
    asm("{ .reg .u64 t; cvta.to.shared.u64 t, %1; cvt.u32.u64 %0, t; }" : "=r"(a) : "l"(p));
    return a;
}
__device__ __forceinline__ void ldsm4(uint32_t* r, uint32_t a) {
    asm volatile("ldmatrix.sync.aligned.m8n8.x4.shared.b16 {%0,%1,%2,%3}, [%4];"
        : "=r"(r[0]), "=r"(r[1]), "=r"(r[2]), "=r"(r[3]) : "r"(a));
}
__device__ __forceinline__ void ldsm2(uint32_t* r, uint32_t a) {
    asm volatile("ldmatrix.sync.aligned.m8n8.x2.shared.b16 {%0,%1}, [%2];"
        : "=r"(r[0]), "=r"(r[1]) : "r"(a));
}
__device__ __forceinline__ void ldsm4t(uint32_t* r, uint32_t a) {
    asm volatile("ldmatrix.sync.aligned.m8n8.x4.trans.shared.b16 {%0,%1,%2,%3}, [%4];"
        : "=r"(r[0]), "=r"(r[1]), "=r"(r[2]), "=r"(r[3]) : "r"(a));
}
__device__ __forceinline__ void ldsm2t(uint32_t* r, uint32_t a) {
    asm volatile("ldmatrix.sync.aligned.m8n8.x2.trans.shared.b16 {%0,%1}, [%2];"
        : "=r"(r[0]), "=r"(r[1]) : "r"(a));
}
__device__ __forceinline__ void mma16816(float* c, const uint32_t* a, const uint32_t* b) {
    asm volatile("mma.sync.aligned.m16n8k16.row.col.f32.f16.f16.f32 "
        "{%0,%1,%2,%3}, {%4,%5,%6,%7}, {%8,%9}, {%0,%1,%2,%3};"
        : "+f"(c[0]), "+f"(c[1]), "+f"(c[2]), "+f"(c[3])
        : "r"(a[0]), "r"(a[1]), "r"(a[2]), "r"(a[3]), "r"(b[0]), "r"(b[1]));
}
__device__ __forceinline__ void mma1688(float* c, const uint32_t* a, uint32_t b0) {
    asm volatile("mma.sync.aligned.m16n8k8.row.col.f32.f16.f16.f32 "
        "{%0,%1,%2,%3}, {%4,%5}, {%6}, {%0,%1,%2,%3};"
        : "+f"(c[0]), "+f"(c[1]), "+f"(c[2]), "+f"(c[3])
        : "r"(a[0]), "r"(a[1]), "r"(b0));
}
__device__ __forceinline__ uint32_t pack2h(float lo_e, float hi_e) { // lo_e -> low half
    uint32_t r; asm("cvt.rn.f16x2.f32 %0, %1, %2;" : "=r"(r) : "f"(hi_e), "f"(lo_e)); return r;
}
__device__ __forceinline__ uint32_t h2exp2u(uint32_t x) {
    uint32_t r; asm("ex2.approx.f16x2 %0, %1;" : "=r"(r) : "r"(x)); return r;
}
__device__ __forceinline__ float2 h2sumf(uint32_t a, uint32_t b) {
    __half2 s = __hadd2(*reinterpret_cast<__half2*>(&a), *reinterpret_cast<__half2*>(&b));
    return __half22float2(s);
}
__device__ __forceinline__ void cpasync16(uint32_t dst, const void* src) {
    asm volatile("cp.async.cg.shared.global [%0], [%1], 16;" :: "r"(dst), "l"(src));
}
#define CP_COMMIT() asm volatile("cp.async.commit_group;" ::: "memory")

// ---------------------------------------------------------------------------
// Kernel 1: Q/K/V projection on tensor cores, PACKED 24-col fp16 outputs.
// ---------------------------------------------------------------------------
#define PR     64
#define PSTR   272
#define WSOFF  (PR * PSTR)
#define PSMTOT (WSOFF + 72 * PSTR)

__global__ __launch_bounds__(128) void proj_kernel(
    const float* __restrict__ x,
    const float* __restrict__ wQ, const float* __restrict__ bQ,
    const float* __restrict__ wK, const float* __restrict__ bK,
    const float* __restrict__ wV, const float* __restrict__ bV)
{
    __shared__ __align__(16) unsigned char psm[PSMTOT];
    __shared__ float bias[72];
    const uint32_t smb = smem_u32(psm);

    int tid = threadIdx.x, l = tid & 31, w = tid >> 5;
    int row0 = blockIdx.x * PR;

    const float4* xg = reinterpret_cast<const float4*>(x + (size_t)row0 * EMB);
    #pragma unroll
    for (int j = 0; j < 16; j++) {
        int i = tid + 128*j;
        int r = i >> 5, c4 = i & 31;
        float4 v = __ldg(xg + (size_t)r*32 + c4);
        uint2 o = make_uint2(pack2h(v.x, v.y), pack2h(v.z, v.w));
        *reinterpret_cast<uint2*>(psm + r*PSTR + c4*8) = o;
    }

    for (int i = tid; i < 72*64; i += 128) {
        int n = i / 64, k2 = i % 64;
        const float* wsrc; int c;
        if (n < 24)      { wsrc = wQ; c = n; }
        else if (n < 48) { wsrc = wK; c = n - 24; }
        else             { wsrc = wV; c = n - 48; }
        float f0 = __ldg(&wsrc[(2*k2)*DH + c]);
        float f1 = __ldg(&wsrc[(2*k2+1)*DH + c]);
        *reinterpret_cast<uint32_t*>(psm + WSOFF + n*PSTR + k2*4) = pack2h(f0, f1);
    }
    if (tid < 24) { bias[tid] = bQ[tid]; bias[24+tid] = bK[tid]; bias[48+tid] = bV[tid]; }
    __syncthreads();

    float c[9][4];
    #pragma unroll
    for (int nt = 0; nt < 9; nt++)
        #pragma unroll
        for (int q = 0; q < 4; q++) c[nt][q] = 0.f;

    int lq = l & 15;
    uint32_t a_off  = (uint32_t)((l & 15)*PSTR + (l >> 4)*16);
    uint32_t b_off  = (uint32_t)(((l & 7) + ((l >> 4) << 3))*PSTR + ((l >> 3) & 1)*16);
    uint32_t b2_off = (uint32_t)((lq & 7)*PSTR + ((lq >> 3) & 1)*16);

    #pragma unroll
    for (int ks = 0; ks < 8; ks++) {
        uint32_t qa[4];
        ldsm4(qa, smb + (uint32_t)(16*w*PSTR + ks*32) + a_off);
        #pragma unroll
        for (int ng = 0; ng < 4; ng++) {
            uint32_t bb[4];
            ldsm4(bb, smb + WSOFF + (uint32_t)(ng*16*PSTR + ks*32) + b_off);
            mma16816(c[2*ng],   qa, bb);
            mma16816(c[2*ng+1], qa, bb + 2);
        }
        uint32_t b2[2];
        ldsm2(b2, smb + WSOFF + (uint32_t)(64*PSTR + ks*32) + b2_off);
        mma16816(c[8], qa, b2);
    }

    int r0 = row0 + 16*w + (l >> 2);
    #pragma unroll
    for (int nt = 0; nt < 9; nt++) {
        int col = nt*8 + 2*(l & 3);
        __half* dst; int cc; float sc;
        if (col < 24)      { dst = Qh_g;        cc = col;      sc = QSCALE; }
        else if (col < 48) { dst = KV_g;        cc = col - 24; sc = 1.f; }
        else               { dst = KV_g + KVH;  cc = col - 48; sc = 1.f; }
        float b0 = bias[col], b1 = bias[col+1];
        *reinterpret_cast<uint32_t*>(dst + (size_t)r0*DH + cc) =
            pack2h((c[nt][0] + b0)*sc, (c[nt][1] + b1)*sc);
        *reinterpret_cast<uint32_t*>(dst + (size_t)(r0+8)*DH + cc) =
            pack2h((c[nt][2] + b0)*sc, (c[nt][3] + b1)*sc);
    }
}

// ---------------------------------------------------------------------------
// Kernel 2: fp16 attention, TQ=64, warp-independent KV-range split (R10
// architecture) with packed-24 global layout and k16+k8 GEMM1 (no pad work).
// Warp w owns KV rows [w*1024,(w+1)*1024), 32 private 32-row double-buffered
// tiles, no CTA barriers in the mainloop.
// ---------------------------------------------------------------------------
#define ROWB  80
#define WTK   32
#define NWT   32
#define MAT32 (WTK*ROWB)          /* 2560 */
#define WBUF  (2*MAT32)           /* 5120: K|V tile */
#define KVOFF (TQ*ROWB)           /* 5120: after Q  */
#define SMTOT (KVOFF + 4*2*WBUF)  /* 46080 */
#define HPW   1792                /* 64*28 floats per warp partial */
#define WOOFF 28672
#define HSTR  28

__global__ __launch_bounds__(128, 4) void attn_kernel(
    const float* __restrict__ wO, const float* __restrict__ bO,
    float* __restrict__ out)
{
    __shared__ __align__(16) unsigned char sm[SMTOT];
    __shared__ float lsum_sh[TQ];
    const uint32_t smb = smem_u32(sm);

    int tid = threadIdx.x, l = tid & 31, w = tid >> 5;
    int b = blockIdx.y, q0 = blockIdx.x * TQ;

    // ---- per-lane staging: 192 x 16B chunks per tile (K 32x48B + V 32x48B)
    const uint32_t mybuf = smb + KVOFF + (uint32_t)w*2*WBUF;
    const int kvrow0 = b*SEQ + w*(SEQ/4);
    const char* gbase = reinterpret_cast<const char*>(KV_g);
    uint32_t goff[6], doff[6];
    #pragma unroll
    for (int j = 0; j < 6; j++) {
        int idx = l + 32*j;               // 0..191
        int m = idx / 96, rem = idx % 96;
        int r = rem / 3, cch = rem % 3;
        goff[j] = (uint32_t)(m*(KVH*2) + (kvrow0 + r)*(DH*2) + cch*16);
        doff[j] = (uint32_t)(m*MAT32 + r*ROWB + cch*16);
    }
    auto stage_tile = [&](int t, uint32_t dst) {
        uint32_t gadd = (uint32_t)(t*(WTK*DH*2));
        #pragma unroll
        for (int j = 0; j < 6; j++)
            cpasync16(dst + doff[j], gbase + goff[j] + gadd);
        CP_COMMIT();
    };
    stage_tile(0, mybuf);

    // ---- stage Q (64 rows x 48B packed)
    #pragma unroll
    for (int j = 0; j < 2; j++) {
        int idx = tid + 128*j;
        if (idx < 192) {
            int r = idx / 3, cch = idx % 3;
            *reinterpret_cast<uint4*>(sm + r*ROWB + cch*16) =
                *reinterpret_cast<const uint4*>(Qh_g + (size_t)(b*SEQ + q0 + r)*DH + cch*8);
        }
    }
    if (tid < TQ) lsum_sh[tid] = 0.f;
    __syncthreads();

    // ---- Q fragments: 4 m-tiles; k0..15 as k16 frag, k16..23 as k8 frag
    uint32_t qa16[4][4], qa8[4][2];
    {
        uint32_t qoff  = (uint32_t)((l & 15)*ROWB + (l >> 4)*16);
        uint32_t qoff2 = (uint32_t)((l & 15)*ROWB + 32);
        #pragma unroll
        for (int mi = 0; mi < 4; mi++) {
            ldsm4(qa16[mi], smb + (uint32_t)(16*mi*ROWB) + qoff);
            ldsm2(qa8[mi],  smb + (uint32_t)(16*mi*ROWB) + qoff2);
        }
    }

    uint32_t k_off  = (uint32_t)(((l & 7) + ((l >> 4) << 3))*ROWB + ((l >> 3) & 1)*16);
    uint32_t k2_off = (uint32_t)((l & 15)*ROWB + 32);
    uint32_t v_off  = (uint32_t)((l & 15)*ROWB + (l >> 4)*16);
    uint32_t v2off  = (uint32_t)((l & 15)*ROWB + 32);

    float h[4][3][4];
    #pragma unroll
    for (int mi = 0; mi < 4; mi++)
        #pragma unroll
        for (int nt = 0; nt < 3; nt++)
            #pragma unroll
            for (int c = 0; c < 4; c++) h[mi][nt][c] = 0.f;
    float rsum[4][2];
    #pragma unroll
    for (int mi = 0; mi < 4; mi++) { rsum[mi][0] = 0.f; rsum[mi][1] = 0.f; }

    // ---- mainloop: warp-private, barrier-free
    #pragma unroll 1
    for (int t = 0; t < NWT; t++) {
        uint32_t buf = mybuf + (uint32_t)(t & 1)*WBUF;
        if (t + 1 < NWT) {
            stage_tile(t + 1, mybuf + (uint32_t)((t+1) & 1)*WBUF);
            asm volatile("cp.async.wait_group 1;" ::: "memory");
        } else {
            asm volatile("cp.async.wait_group 0;" ::: "memory");
        }
        __syncwarp();

        #pragma unroll
        for (int ng = 0; ng < 2; ng++) {        // 16 KV rows each
            uint32_t kh0[4], kh1b[2], vh[4], vh2[2];
            uint32_t kb = buf + (uint32_t)(ng*16*ROWB);
            ldsm4(kh0,  kb + k_off);            // K rows, k 0..15
            ldsm2(kh1b, kb + k2_off);           // K rows, k 16..23
            uint32_t vb = buf + MAT32 + (uint32_t)(ng*16*ROWB);
            ldsm4t(vh,  vb + v_off);            // V k-rows, n 0..15
            ldsm2t(vh2, vb + v2off);            // V k-rows, n 16..23

            #pragma unroll
            for (int mi = 0; mi < 4; mi++) {
                float s2[8] = {0.f,0.f,0.f,0.f,0.f,0.f,0.f,0.f};
                mma16816(s2,     qa16[mi], kh0);
                mma16816(s2 + 4, qa16[mi], kh0 + 2);
                mma1688(s2,     qa8[mi], kh1b[0]);
                mma1688(s2 + 4, qa8[mi], kh1b[1]);

                uint32_t pa[4];
                pa[0] = h2exp2u(pack2h(s2[0], s2[1]));
                pa[1] = h2exp2u(pack2h(s2[2], s2[3]));
                pa[2] = h2exp2u(pack2h(s2[4], s2[5]));
                pa[3] = h2exp2u(pack2h(s2[6], s2[7]));

                float2 f0 = h2sumf(pa[0], pa[2]);
                float2 f1 = h2sumf(pa[1], pa[3]);
                rsum[mi][0] += f0.x + f0.y;
                rsum[mi][1] += f1.x + f1.y;

                mma16816(h[mi][0], pa, vh);
                mma16816(h[mi][1], pa, vh + 2);
                mma16816(h[mi][2], pa, vh2);
            }
        }
    }

    __syncthreads();   // all warps done: staging buffers dead

    // ---- per-warp H partials + lsum atomics
    float* Hp = reinterpret_cast<float*>(sm);
    {
        float* base = Hp + w*HPW;
        #pragma unroll
        for (int mi = 0; mi < 4; mi++) {
            int row = 16*mi + (l >> 2);
            #pragma unroll
            for (int nt = 0; nt < 3; nt++) {
                int col = nt*8 + 2*(l & 3);
                base[row*HSTR + col]       = h[mi][nt][0];
                base[row*HSTR + col + 1]   = h[mi][nt][1];
                base[(row+8)*HSTR + col]   = h[mi][nt][2];
                base[(row+8)*HSTR + col+1] = h[mi][nt][3];
            }
        }
        #pragma unroll
        for (int mi = 0; mi < 4; mi++) {
            float r0 = rsum[mi][0], r1 = rsum[mi][1];
            r0 += __shfl_xor_sync(0xffffffffu, r0, 1);
            r0 += __shfl_xor_sync(0xffffffffu, r0, 2);
            r1 += __shfl_xor_sync(0xffffffffu, r1, 1);
            r1 += __shfl_xor_sync(0xffffffffu, r1, 2);
            if ((l & 3) == 0) {
                atomicAdd(&lsum_sh[16*mi + (l >> 2)],     r0);
                atomicAdd(&lsum_sh[16*mi + 8 + (l >> 2)], r1);
            }
        }
    }
    __syncthreads();

    // ---- reduce 4 warp partials + normalize; stage wO/bO
    for (int i = tid; i < TQ*DH; i += 128) {
        int q = i / DH, d = i % DH;
        float v = Hp[q*HSTR + d] + Hp[HPW + q*HSTR + d]
                + Hp[2*HPW + q*HSTR + d] + Hp[3*HPW + q*HSTR + d];
        Hp[q*HSTR + d] = v * __fdividef(1.f, lsum_sh[q]);
    }
    float* wOs = reinterpret_cast<float*>(sm + WOOFF);
    float* bOs = wOs + DH*EMB;
    for (int i = tid; i < DH*EMB; i += 128) wOs[i] = wO[i];
    if (tid < EMB) bOs[tid] = bO[tid];
    __syncthreads();

    // ---- fused output projection
    int e = tid;
    float wcol[DH];
    #pragma unroll
    for (int d = 0; d < DH; d++) wcol[d] = wOs[d*EMB + e];
    float be = bOs[e];
    float* op = out + ((size_t)(b*SEQ + q0))*EMB + e;
    for (int q = 0; q < TQ; q++) {
        const float4* hr = reinterpret_cast<const float4*>(Hp + q*HSTR);
        float acc = be;
        #pragma unroll
        for (int d4 = 0; d4 < 6; d4++) {
            float4 hv = hr[d4];
            acc = fmaf(hv.x, wcol[4*d4],   acc);
            acc = fmaf(hv.y, wcol[4*d4+1], acc);
            acc = fmaf(hv.z, wcol[4*d4+2], acc);
            acc = fmaf(hv.w, wcol[4*d4+3], acc);
        }
        op[(size_t)q*EMB] = acc;
    }
}

// ---------------------------------------------------------------------------
extern "C" void kernel_launch(void* const* d_in, const int* in_sizes, int n_in,
                              void* d_out, int out_size)
{
    const float* x  = (const float*)d_in[0];
    const float* wQ = (const float*)d_in[1];
    const float* bQ = (const float*)d_in[2];
    const float* wK = (const float*)d_in[3];
    const float* bK = (const float*)d_in[4];
    const float* wV = (const float*)d_in[5];
    const float* bV = (const float*)d_in[6];
    const float* wO = (const float*)d_in[7];
    const float* bO = (const float*)d_in[8];
    float* out = (float*)d_out;

    proj_kernel<<<BATCH*SEQ/PR, 128>>>(x, wQ, bQ, wK, bK, wV, bV);
    attn_kernel<<<dim3(SEQ/TQ, BATCH), 128>>>(wO, bO, out);
}

// round 17
// speedup vs baseline: 2.0893x; 1.0765x over previous
#include <cuda_runtime.h>
#include <cuda_fp16.h>
#include <cstdint>

#define BATCH 8
#define SEQ   4096
#define EMB   128
#define DH    24
#define DPAD  32
#define TQ    64
// (1/sqrt(128)) * log2(e): folded into Q so softmax is exp2
#define QSCALE (0.08838834764831845f * 1.4426950408889634f)

// Projected tensors, fp16, DH padded 24 -> 32 with zeros.
__device__ __align__(16) __half Qh_g[BATCH*SEQ*DPAD];
__device__ __align__(16) __half Kh_g[BATCH*SEQ*DPAD];
__device__ __align__(16) __half Vh_g[BATCH*SEQ*DPAD];

// ---------------- helpers ----------------------------------------------------
__device__ __forceinline__ uint32_t smem_u32(const void* p) {
    uint32_t a;
    asm("{ .reg .u64 t; cvta.to.shared.u64 t, %1; cvt.u32.u64 %0, t; }" : "=r"(a) : "l"(p));
    return a;
}
__device__ __forceinline__ void ldsm4(uint32_t* r, uint32_t a) {
    asm volatile("ldmatrix.sync.aligned.m8n8.x4.shared.b16 {%0,%1,%2,%3}, [%4];"
        : "=r"(r[0]), "=r"(r[1]), "=r"(r[2]), "=r"(r[3]) : "r"(a));
}
__device__ __forceinline__ void ldsm2(uint32_t* r, uint32_t a) {
    asm volatile("ldmatrix.sync.aligned.m8n8.x2.shared.b16 {%0,%1}, [%2];"
        : "=r"(r[0]), "=r"(r[1]) : "r"(a));
}
__device__ __forceinline__ void ldsm4t(uint32_t* r, uint32_t a) {
    asm volatile("ldmatrix.sync.aligned.m8n8.x4.trans.shared.b16 {%0,%1,%2,%3}, [%4];"
        : "=r"(r[0]), "=r"(r[1]), "=r"(r[2]), "=r"(r[3]) : "r"(a));
}
__device__ __forceinline__ void ldsm2t(uint32_t* r, uint32_t a) {
    asm volatile("ldmatrix.sync.aligned.m8n8.x2.trans.shared.b16 {%0,%1}, [%2];"
        : "=r"(r[0]), "=r"(r[1]) : "r"(a));
}
// f32-accumulator mma (projection + GEMM2)
__device__ __forceinline__ void mma16816(float* c, const uint32_t* a, const uint32_t* b) {
    asm volatile("mma.sync.aligned.m16n8k16.row.col.f32.f16.f16.f32 "
        "{%0,%1,%2,%3}, {%4,%5,%6,%7}, {%8,%9}, {%0,%1,%2,%3};"
        : "+f"(c[0]), "+f"(c[1]), "+f"(c[2]), "+f"(c[3])
        : "r"(a[0]), "r"(a[1]), "r"(a[2]), "r"(a[3]), "r"(b[0]), "r"(b[1]));
}
// f16-accumulator mma (GEMM1: S stays packed fp16x2 = GEMM2 A-fragment layout)
__device__ __forceinline__ void mma16816h(uint32_t* c, const uint32_t* a, const uint32_t* b) {
    asm volatile("mma.sync.aligned.m16n8k16.row.col.f16.f16.f16.f16 "
        "{%0,%1}, {%2,%3,%4,%5}, {%6,%7}, {%0,%1};"
        : "+r"(c[0]), "+r"(c[1])
        : "r"(a[0]), "r"(a[1]), "r"(a[2]), "r"(a[3]), "r"(b[0]), "r"(b[1]));
}
__device__ __forceinline__ uint32_t pack2h(float lo_e, float hi_e) { // lo_e -> low half
    uint32_t r; asm("cvt.rn.f16x2.f32 %0, %1, %2;" : "=r"(r) : "f"(hi_e), "f"(lo_e)); return r;
}
__device__ __forceinline__ uint32_t hadd2u(uint32_t a, uint32_t b) {
    uint32_t r; asm("add.f16x2 %0, %1, %2;" : "=r"(r) : "r"(a), "r"(b)); return r;
}
__device__ __forceinline__ uint32_t h2exp2u(uint32_t x) {
    uint32_t r; asm("ex2.approx.f16x2 %0, %1;" : "=r"(r) : "r"(x)); return r;
}
__device__ __forceinline__ float2 h2sumf(uint32_t a, uint32_t b) {
    __half2 s = __hadd2(*reinterpret_cast<__half2*>(&a), *reinterpret_cast<__half2*>(&b));
    return __half22float2(s);
}
__device__ __forceinline__ void cpasync16(uint32_t dst, const void* src) {
    asm volatile("cp.async.cg.shared.global [%0], [%1], 16;" :: "r"(dst), "l"(src));
}
#define CP_COMMIT() asm volatile("cp.async.commit_group;" ::: "memory")

// ---------------------------------------------------------------------------
// Kernel 1: Q/K/V projection on tensor cores.  Epilogue stages biased fp16
// results in smem, then writes COALESCED uint4 stores (pad cols as zeros).
// ---------------------------------------------------------------------------
#define PR     64
#define PSTR   272
#define WSOFF  (PR * PSTR)
#define PSMTOT (WSOFF + 72 * PSTR)
#define HST    176                /* epilogue staging stride (conflict-free) */

__global__ __launch_bounds__(128) void proj_kernel(
    const float* __restrict__ x,
    const float* __restrict__ wQ, const float* __restrict__ bQ,
    const float* __restrict__ wK, const float* __restrict__ bK,
    const float* __restrict__ wV, const float* __restrict__ bV)
{
    __shared__ __align__(16) unsigned char psm[PSMTOT];
    __shared__ float bias[72];
    const uint32_t smb = smem_u32(psm);

    int tid = threadIdx.x, l = tid & 31, w = tid >> 5;
    int row0 = blockIdx.x * PR;

    const float4* xg = reinterpret_cast<const float4*>(x + (size_t)row0 * EMB);
    #pragma unroll
    for (int j = 0; j < 16; j++) {
        int i = tid + 128*j;
        int r = i >> 5, c4 = i & 31;
        float4 v = __ldg(xg + (size_t)r*32 + c4);
        uint2 o = make_uint2(pack2h(v.x, v.y), pack2h(v.z, v.w));
        *reinterpret_cast<uint2*>(psm + r*PSTR + c4*8) = o;
    }

    for (int i = tid; i < 72*64; i += 128) {
        int n = i / 64, k2 = i % 64;
        const float* wsrc; int c;
        if (n < 24)      { wsrc = wQ; c = n; }
        else if (n < 48) { wsrc = wK; c = n - 24; }
        else             { wsrc = wV; c = n - 48; }
        float f0 = __ldg(&wsrc[(2*k2)*DH + c]);
        float f1 = __ldg(&wsrc[(2*k2+1)*DH + c]);
        *reinterpret_cast<uint32_t*>(psm + WSOFF + n*PSTR + k2*4) = pack2h(f0, f1);
    }
    if (tid < 24) { bias[tid] = bQ[tid]; bias[24+tid] = bK[tid]; bias[48+tid] = bV[tid]; }
    __syncthreads();

    float c[9][4];
    #pragma unroll
    for (int nt = 0; nt < 9; nt++)
        #pragma unroll
        for (int q = 0; q < 4; q++) c[nt][q] = 0.f;

    int lq = l & 15;
    uint32_t a_off  = (uint32_t)((l & 15)*PSTR + (l >> 4)*16);
    uint32_t b_off  = (uint32_t)(((l & 7) + ((l >> 4) << 3))*PSTR + ((l >> 3) & 1)*16);
    uint32_t b2_off = (uint32_t)((lq & 7)*PSTR + ((lq >> 3) & 1)*16);

    #pragma unroll
    for (int ks = 0; ks < 8; ks++) {
        uint32_t qa[4];
        ldsm4(qa, smb + (uint32_t)(16*w*PSTR + ks*32) + a_off);
        #pragma unroll
        for (int ng = 0; ng < 4; ng++) {
            uint32_t bb[4];
            ldsm4(bb, smb + WSOFF + (uint32_t)(ng*16*PSTR + ks*32) + b_off);
            mma16816(c[2*ng],   qa, bb);
            mma16816(c[2*ng+1], qa, bb + 2);
        }
        uint32_t b2[2];
        ldsm2(b2, smb + WSOFF + (uint32_t)(64*PSTR + ks*32) + b2_off);
        mma16816(c[8], qa, b2);
    }
    __syncthreads();     // x-region reads complete; reuse as epilogue staging

    // ---- stage biased/scaled fp16 pairs (rows x 72 halves, HST stride)
    {
        int r0 = 16*w + (l >> 2);
        #pragma unroll
        for (int nt = 0; nt < 9; nt++) {
            int col = nt*8 + 2*(l & 3);
            float sc = (col < 24) ? QSCALE : 1.f;
            float b0 = bias[col], b1 = bias[col+1];
            *reinterpret_cast<uint32_t*>(psm + r0*HST + col*2) =
                pack2h((c[nt][0] + b0)*sc, (c[nt][1] + b1)*sc);
            *reinterpret_cast<uint32_t*>(psm + (r0+8)*HST + col*2) =
                pack2h((c[nt][2] + b0)*sc, (c[nt][3] + b1)*sc);
        }
    }
    __syncthreads();

    // ---- coalesced output: 3 arrays x 64 rows x 4 uint4 (c8==3 -> zero pad)
    #pragma unroll
    for (int j = 0; j < 6; j++) {
        int i = tid + 128*j;                  // 0..767
        int arr = i >> 8, rem = i & 255, r = rem >> 2, c8 = rem & 3;
        uint4 v = make_uint4(0u, 0u, 0u, 0u);
        if (c8 < 3)
            v = *reinterpret_cast<const uint4*>(psm + r*HST + arr*48 + c8*16);
        __half* dst = (arr == 0) ? Qh_g : (arr == 1) ? Kh_g : Vh_g;
        *reinterpret_cast<uint4*>(dst + (size_t)(row0 + r)*DPAD + c8*8) = v;
    }
}

// ---------------------------------------------------------------------------
// Kernel 2: fp16 attention, warp-independent KV-range split (R10 base).
// GEMM1 uses f16-accumulator mma: S emerges already packed fp16x2 in the
// GEMM2 A-fragment layout -> exp2 directly, no cvt packs, and the two
// k-halves accumulate independently (shorter RAW chain).
// ---------------------------------------------------------------------------
#define ROWB  80
#define WTK   32
#define NWT   32
#define MAT32 (WTK*ROWB)          /* 2560 */
#define WBUF  (2*MAT32)           /* 5120 : K|V tile */
#define KVOFF (TQ*ROWB)           /* 5120 : after Q  */
#define SMTOT (KVOFF + 4*2*WBUF)  /* 46080 */
#define HPW   1792                /* 64*28 floats per warp partial */
#define WOOFF 28672
#define HSTR  28

__global__ __launch_bounds__(128, 4) void attn_kernel(
    const float* __restrict__ wO, const float* __restrict__ bO,
    float* __restrict__ out)
{
    __shared__ __align__(16) unsigned char sm[SMTOT];
    __shared__ float lsum_sh[TQ];
    const uint32_t smb = smem_u32(sm);

    int tid = threadIdx.x, l = tid & 31, w = tid >> 5;
    int b = blockIdx.y, q0 = blockIdx.x * TQ;

    const uint32_t mybuf = smb + KVOFF + (uint32_t)w*2*WBUF;
    const int kvrow0 = b*SEQ + w*(SEQ/4);

    int st_r = l >> 2, st_c = (l & 3)*16;
    auto stage_tile = [&](int t, uint32_t dst) {
        const __half* ks = Kh_g + ((size_t)(kvrow0 + t*WTK + st_r))*DPAD + (st_c >> 1);
        const __half* vs = Vh_g + ((size_t)(kvrow0 + t*WTK + st_r))*DPAD + (st_c >> 1);
        #pragma unroll
        for (int j = 0; j < 4; j++) {
            cpasync16(dst + (st_r + 8*j)*ROWB + st_c, ks + (size_t)(8*j)*DPAD);
            cpasync16(dst + MAT32 + (st_r + 8*j)*ROWB + st_c, vs + (size_t)(8*j)*DPAD);
        }
        CP_COMMIT();
    };
    stage_tile(0, mybuf);

    {   // stage Q (64 x 32 fp16)
        int rowg = b*SEQ + q0;
        #pragma unroll
        for (int j = 0; j < 2; j++) {
            int i = tid + 128*j;
            int r = i >> 2, c4 = i & 3;
            *reinterpret_cast<uint4*>(sm + r*ROWB + c4*16) =
                *reinterpret_cast<const uint4*>(Qh_g + ((size_t)(rowg + r)*DPAD + c4*8));
        }
    }
    if (tid < TQ) lsum_sh[tid] = 0.f;
    __syncthreads();

    // ---- Q fragments: 4 m-tiles x 2 k-slices
    uint32_t qa[4][2][4];
    {
        uint32_t qoff = (uint32_t)((l & 15)*ROWB + (l >> 4)*16);
        #pragma unroll
        for (int mi = 0; mi < 4; mi++)
            #pragma unroll
            for (int ks = 0; ks < 2; ks++)
                ldsm4(qa[mi][ks], smb + (uint32_t)(16*mi*ROWB + ks*32) + qoff);
    }

    uint32_t k_off = (uint32_t)(((l & 7) + ((l >> 4) << 3))*ROWB + ((l >> 3) & 1)*16);
    uint32_t v_off = (uint32_t)((l & 15)*ROWB + (l >> 4)*16);
    uint32_t v2off = (uint32_t)((l & 15)*ROWB + 32);

    float h[4][3][4];
    #pragma unroll
    for (int mi = 0; mi < 4; mi++)
        #pragma unroll
        for (int nt = 0; nt < 3; nt++)
            #pragma unroll
            for (int c = 0; c < 4; c++) h[mi][nt][c] = 0.f;
    float rsum[4][2];
    #pragma unroll
    for (int mi = 0; mi < 4; mi++) { rsum[mi][0] = 0.f; rsum[mi][1] = 0.f; }

    // ---- mainloop: warp-private, barrier-free
    #pragma unroll 1
    for (int t = 0; t < NWT; t++) {
        uint32_t buf = mybuf + (uint32_t)(t & 1)*WBUF;
        if (t + 1 < NWT) {
            stage_tile(t + 1, mybuf + (uint32_t)((t+1) & 1)*WBUF);
            asm volatile("cp.async.wait_group 1;" ::: "memory");
        } else {
            asm volatile("cp.async.wait_group 0;" ::: "memory");
        }
        __syncwarp();

        #pragma unroll
        for (int ng = 0; ng < 2; ng++) {        // 16 KV rows each
            uint32_t kh0[4], kh1[4], vh[4], vh2[2];
            uint32_t kb = buf + (uint32_t)(ng*16*ROWB);
            ldsm4(kh0, kb + k_off);             // K rows, k 0..15
            ldsm4(kh1, kb + 32 + k_off);        // K rows, k 16..31 (pad 0)
            uint32_t vb = buf + MAT32 + (uint32_t)(ng*16*ROWB);
            ldsm4t(vh,  vb + v_off);            // V k-rows, n 0..15
            ldsm2t(vh2, vb + v2off);            // V k-rows, n 16..23

            #pragma unroll
            for (int mi = 0; mi < 4; mi++) {
                uint32_t sA[4] = {0u,0u,0u,0u}, sB[4] = {0u,0u,0u,0u};
                mma16816h(sA,     qa[mi][0], kh0);       // n0..7,  k lo
                mma16816h(sA + 2, qa[mi][0], kh0 + 2);   // n8..15, k lo
                mma16816h(sB,     qa[mi][1], kh1);       // n0..7,  k hi
                mma16816h(sB + 2, qa[mi][1], kh1 + 2);   // n8..15, k hi

                uint32_t pa[4];
                pa[0] = h2exp2u(hadd2u(sA[0], sB[0]));   // row r,   A k 2c
                pa[1] = h2exp2u(hadd2u(sA[1], sB[1]));   // row r+8, A k 2c
                pa[2] = h2exp2u(hadd2u(sA[2], sB[2]));   // row r,   A k 8+2c
                pa[3] = h2exp2u(hadd2u(sA[3], sB[3]));   // row r+8, A k 8+2c

                float2 f0 = h2sumf(pa[0], pa[2]);
                float2 f1 = h2sumf(pa[1], pa[3]);
                rsum[mi][0] += f0.x + f0.y;
                rsum[mi][1] += f1.x + f1.y;

                mma16816(h[mi][0], pa, vh);
                mma16816(h[mi][1], pa, vh + 2);
                mma16816(h[mi][2], pa, vh2);
            }
        }
    }

    __syncthreads();   // all warps done: staging buffers dead

    // ---- per-warp H partials + lsum atomics
    float* Hp = reinterpret_cast<float*>(sm);
    {
        float* base = Hp + w*HPW;
        #pragma unroll
        for (int mi = 0; mi < 4; mi++) {
            int row = 16*mi + (l >> 2);
            #pragma unroll
            for (int nt = 0; nt < 3; nt++) {
                int col = nt*8 + 2*(l & 3);
                base[row*HSTR + col]       = h[mi][nt][0];
                base[row*HSTR + col + 1]   = h[mi][nt][1];
                base[(row+8)*HSTR + col]   = h[mi][nt][2];
                base[(row+8)*HSTR + col+1] = h[mi][nt][3];
            }
        }
        #pragma unroll
        for (int mi = 0; mi < 4; mi++) {
            float r0 = rsum[mi][0], r1 = rsum[mi][1];
            r0 += __shfl_xor_sync(0xffffffffu, r0, 1);
            r0 += __shfl_xor_sync(0xffffffffu, r0, 2);
            r1 += __shfl_xor_sync(0xffffffffu, r1, 1);
            r1 += __shfl_xor_sync(0xffffffffu, r1, 2);
            if ((l & 3) == 0) {
                atomicAdd(&lsum_sh[16*mi + (l >> 2)],     r0);
                atomicAdd(&lsum_sh[16*mi + 8 + (l >> 2)], r1);
            }
        }
    }
    __syncthreads();

    // ---- reduce 4 warp partials + normalize; stage wO/bO
    for (int i = tid; i < TQ*DH; i += 128) {
        int q = i / DH, d = i % DH;
        float v = Hp[q*HSTR + d] + Hp[HPW + q*HSTR + d]
                + Hp[2*HPW + q*HSTR + d] + Hp[3*HPW + q*HSTR + d];
        Hp[q*HSTR + d] = v * __fdividef(1.f, lsum_sh[q]);
    }
    float* wOs = reinterpret_cast<float*>(sm + WOOFF);
    float* bOs = wOs + DH*EMB;
    for (int i = tid; i < DH*EMB; i += 128) wOs[i] = wO[i];
    if (tid < EMB) bOs[tid] = bO[tid];
    __syncthreads();

    // ---- fused output projection
    int e = tid;
    float wcol[DH];
    #pragma unroll
    for (int d = 0; d < DH; d++) wcol[d] = wOs[d*EMB + e];
    float be = bOs[e];
    float* op = out + ((size_t)(b*SEQ + q0))*EMB + e;
    for (int q = 0; q < TQ; q++) {
        const float4* hr = reinterpret_cast<const float4*>(Hp + q*HSTR);
        float acc = be;
        #pragma unroll
        for (int d4 = 0; d4 < 6; d4++) {
            float4 hv = hr[d4];
            acc = fmaf(hv.x, wcol[4*d4],   acc);
            acc = fmaf(hv.y, wcol[4*d4+1], acc);
            acc = fmaf(hv.z, wcol[4*d4+2], acc);
            acc = fmaf(hv.w, wcol[4*d4+3], acc);
        }
        op[(size_t)q*EMB] = acc;
    }
}

// ---------------------------------------------------------------------------
extern "C" void kernel_launch(void* const* d_in, const int* in_sizes, int n_in,
                              void* d_out, int out_size)
{
    const float* x  = (const float*)d_in[0];
    const float* wQ = (const float*)d_in[1];
    const float* bQ = (const float*)d_in[2];
    const float* wK = (const float*)d_in[3];
    const float* bK = (const float*)d_in[4];
    const float* wV = (const float*)d_in[5];
    const float* bV = (const float*)d_in[6];
    const float* wO = (const float*)d_in[7];
    const float* bO = (const float*)d_in[8];
    float* out = (float*)d_out;

    proj_kernel<<<BATCH*SEQ/PR, 128>>>(x, wQ, bQ, wK, bK, wV, bV);
    attn_kernel<<<dim3(SEQ/TQ, BATCH), 128>>>(wO, bO, out);
}